// round 3
// baseline (speedup 1.0000x reference)
#include <cuda_runtime.h>
#include <math.h>

#define NN 50000
#define NE 800000
#define DIN 64
#define EIN 32
#define EOUT 64
#define DOUT 64

// scratch (device globals: no allocation allowed)
__device__ float g_logit[NE];
__device__ float g_m[NN];
__device__ float g_denom[NN];
__device__ float g_aggraw[NN * 64];

__device__ __forceinline__ void atomicMaxF(float* addr, float v) {
    if (v >= 0.0f) atomicMax((int*)addr, __float_as_int(v));
    else           atomicMin((unsigned int*)addr, __float_as_uint(v));
}

// ---------------------------------------------------------------- init
__global__ void k_init() {
    int i = blockIdx.x * 256 + threadIdx.x;
    if (i < NN) { g_m[i] = -INFINITY; g_denom[i] = 0.0f; }
    if (i < NN * 64) g_aggraw[i] = 0.0f;
}

// ---------------------------------------------------------------- edge kernel
// 64 edges per CTA, 256 threads. smem layout (floats):
//   s_in  : 160*65 = 10400   (e_in transposed [k][e]; later reused for We2 [j][o] stride 65)
//   s_h   : 256*65 = 16640   (hidden transposed [j][e], after relu+bias)
//   s_w   :   8*256 = 2048   (layer-1 weight chunk)
//   s_b1  : 256  (bcat = [be1;ba1])
//   s_be2 : 64, s_wa2 : 128, s_ba2 : 1
//   s_src : 64 (int), s_dst: 64 (int)
#define EDGE_SMEM_FLOATS 29668
#define EDGE_SMEM_BYTES (EDGE_SMEM_FLOATS * 4)

__global__ void __launch_bounds__(256, 1) k_edge(
    const float* __restrict__ nf, const float* __restrict__ ef,
    const int* __restrict__ src, const int* __restrict__ dst,
    const float* __restrict__ We1, const float* __restrict__ be1,
    const float* __restrict__ We2, const float* __restrict__ be2,
    const float* __restrict__ Wa1, const float* __restrict__ ba1,
    const float* __restrict__ Wa2, const float* __restrict__ ba2,
    float* __restrict__ out_e)
{
    extern __shared__ float smem[];
    float* s_in  = smem;             // 10400
    float* s_h   = smem + 10400;     // 16640
    float* s_w   = smem + 27040;     // 2048
    float* s_b1  = smem + 29088;     // 256
    float* s_be2 = smem + 29344;     // 64
    float* s_wa2 = smem + 29408;     // 128
    float* s_ba2 = smem + 29536;     // 1
    int*   s_src = (int*)(smem + 29540);  // 64
    int*   s_dst = (int*)(smem + 29604);  // 64

    const int tid  = threadIdx.x;
    const int lane = tid & 31;
    const int w    = tid >> 5;        // warp id 0..7
    const int e0   = blockIdx.x * 64;

    if (tid < 64)        s_src[tid]      = src[e0 + tid];
    else if (tid < 128)  s_dst[tid - 64] = dst[e0 + tid - 64];
    s_b1[tid] = (tid < 128) ? be1[tid] : ba1[tid - 128];
    if (tid < 64)  s_be2[tid] = be2[tid];
    if (tid < 128) s_wa2[tid] = Wa2[tid];
    if (tid == 0)  s_ba2[0]   = ba2[0];
    __syncthreads();

    // gather e_in = [nf[src] | nf[dst] | ef] transposed into s_in[k][e]
    #pragma unroll
    for (int p = 0; p < 40; ++p) {
        int lin = p * 256 + tid;          // 64*160 = 10240 total
        int e = lin / 160;
        int k = lin - e * 160;
        float v;
        if (k < 64)       v = nf[s_src[e] * 64 + k];
        else if (k < 128) v = nf[s_dst[e] * 64 + (k - 64)];
        else              v = ef[(e0 + e) * 32 + (k - 128)];
        s_in[k * 65 + e] = v;
    }

    // GEMM1: hidden[64 e][256 j] = e_in @ [We1|Wa1], K=160
    float acc[8][8];
    #pragma unroll
    for (int i = 0; i < 8; i++)
        #pragma unroll
        for (int j = 0; j < 8; j++) acc[i][j] = 0.0f;

    for (int k0 = 0; k0 < 160; k0 += 8) {
        __syncthreads();
        #pragma unroll
        for (int p = 0; p < 8; p++) {
            int k = k0 + p;
            s_w[p * 256 + tid] = (tid < 128) ? We1[k * 128 + tid]
                                             : Wa1[k * 128 + (tid - 128)];
        }
        __syncthreads();
        #pragma unroll
        for (int kk = 0; kk < 8; kk++) {
            float a[8], b[8];
            #pragma unroll
            for (int i = 0; i < 8; i++) a[i] = s_in[(k0 + kk) * 65 + w * 8 + i];
            #pragma unroll
            for (int jj = 0; jj < 8; jj++) b[jj] = s_w[kk * 256 + lane + 32 * jj];
            #pragma unroll
            for (int i = 0; i < 8; i++)
                #pragma unroll
                for (int jj = 0; jj < 8; jj++)
                    acc[i][jj] = fmaf(a[i], b[jj], acc[i][jj]);
        }
    }
    __syncthreads();

    // relu(acc + bias) -> s_h[j][e] ; load We2 into s_in region (stride 65)
    #pragma unroll
    for (int jj = 0; jj < 8; jj++) {
        int j = lane + 32 * jj;
        float bv = s_b1[j];
        #pragma unroll
        for (int i = 0; i < 8; i++) {
            float v = acc[i][jj] + bv;
            s_h[j * 65 + w * 8 + i] = v > 0.0f ? v : 0.0f;
        }
    }
    float* s_w2 = s_in;
    #pragma unroll
    for (int p = 0; p < 32; p++) {
        int lin = p * 256 + tid;          // 128*64 = 8192
        int j = lin >> 6, o = lin & 63;
        s_w2[j * 65 + o] = We2[lin];
    }
    __syncthreads();

    // GEMM2: uh_e[64 e][64 o] = relu_h[:, :128] @ We2, K=128
    float acc2[8][2];
    #pragma unroll
    for (int i = 0; i < 8; i++) { acc2[i][0] = 0.0f; acc2[i][1] = 0.0f; }
    #pragma unroll 4
    for (int j = 0; j < 128; j++) {
        float b0 = s_w2[j * 65 + lane];
        float b1 = s_w2[j * 65 + lane + 32];
        #pragma unroll
        for (int i = 0; i < 8; i++) {
            float a = s_h[j * 65 + w * 8 + i];
            acc2[i][0] = fmaf(a, b0, acc2[i][0]);
            acc2[i][1] = fmaf(a, b1, acc2[i][1]);
        }
    }
    float bb0 = s_be2[lane], bb1 = s_be2[lane + 32];
    #pragma unroll
    for (int i = 0; i < 8; i++) {
        int eg = e0 + w * 8 + i;
        out_e[eg * 64 + lane]      = acc2[i][0] + bb0;
        out_e[eg * 64 + lane + 32] = acc2[i][1] + bb1;
    }

    // attention logit: relu_h[:, 128:256] . Wa2 + ba2  (threads 0..63, one edge each)
    if (tid < 64) {
        float lg = s_ba2[0];
        #pragma unroll 4
        for (int j = 0; j < 128; j++)
            lg = fmaf(s_h[(128 + j) * 65 + tid], s_wa2[j], lg);
        g_logit[e0 + tid] = lg;
        atomicMaxF(&g_m[s_dst[tid]], lg);
    }
}

// ---------------------------------------------------------------- softmax + scatter
// one warp per edge; warp-uniform broadcast loads (no shuffles)
__global__ void k_soft(const float* __restrict__ out_e, const int* __restrict__ dst) {
    int wid = (blockIdx.x * blockDim.x + threadIdx.x) >> 5;
    if (wid >= NE) return;
    int lane = threadIdx.x & 31;
    int e = wid;
    int d = dst[e];                               // broadcast (uniform addr)
    float ex = expf(g_logit[e] - g_m[d]);         // broadcast
    if (lane == 0) atomicAdd(&g_denom[d], ex);
    const float2* pe = (const float2*)(out_e + (size_t)e * 64);
    float2 v = pe[lane];
    atomicAdd(&g_aggraw[d * 64 + 2 * lane],     v.x * ex);
    atomicAdd(&g_aggraw[d * 64 + 2 * lane + 1], v.y * ex);
}

// ---------------------------------------------------------------- node kernel
// 64 nodes per CTA, 256 threads.
#define NODE_SMEM_FLOATS 24960
#define NODE_SMEM_BYTES (NODE_SMEM_FLOATS * 4)

__global__ void __launch_bounds__(256, 1) k_node(
    const float* __restrict__ nf,
    const float* __restrict__ Wn1, const float* __restrict__ bn1,
    const float* __restrict__ Wn2, const float* __restrict__ bn2,
    float* __restrict__ out_n)
{
    extern __shared__ float smem[];
    float* s_x   = smem;           // 8320 (x [k][n]; reused as hidden [j][n])
    float* s_w   = smem + 8320;    // 16384 (Wn1; reused for Wn2)
    float* s_b1  = smem + 24704;   // 128
    float* s_b2  = smem + 24832;   // 64
    float* s_inv = smem + 24896;   // 64

    const int tid = threadIdx.x, lane = tid & 31, w = tid >> 5;
    const int n0 = blockIdx.x * 64;

    if (tid < 128)      s_b1[tid]       = bn1[tid];
    else if (tid < 192) s_b2[tid - 128] = bn2[tid - 128];
    if (tid < 64) {
        int ng = n0 + tid;
        s_inv[tid] = (ng < NN) ? 1.0f / fmaxf(g_denom[ng], 1e-38f) : 0.0f;
    }
    #pragma unroll
    for (int p = 0; p < 64; p++) {              // Wn1: 128*128
        int lin = p * 256 + tid;
        s_w[lin] = Wn1[lin];
    }
    __syncthreads();

    // x = [agg | nf] transposed into s_x[k][n]
    #pragma unroll
    for (int p = 0; p < 32; p++) {
        int lin = p * 256 + tid;                // 64*128
        int n = lin >> 7, k = lin & 127;
        int ng = n0 + n;
        float v = 0.0f;
        if (ng < NN) {
            if (k < 64) v = g_aggraw[ng * 64 + k] * s_inv[n];
            else        v = nf[ng * 64 + (k - 64)];
        }
        s_x[k * 65 + n] = v;
    }
    __syncthreads();

    // GEMM_A: hidden[64 n][128 j], K=128
    float acc[8][4];
    #pragma unroll
    for (int i = 0; i < 8; i++)
        #pragma unroll
        for (int j = 0; j < 4; j++) acc[i][j] = 0.0f;
    #pragma unroll 4
    for (int k = 0; k < 128; k++) {
        float a[8], b[4];
        #pragma unroll
        for (int i = 0; i < 8; i++) a[i] = s_x[k * 65 + w * 8 + i];
        #pragma unroll
        for (int jj = 0; jj < 4; jj++) b[jj] = s_w[k * 128 + lane + 32 * jj];
        #pragma unroll
        for (int i = 0; i < 8; i++)
            #pragma unroll
            for (int jj = 0; jj < 4; jj++)
                acc[i][jj] = fmaf(a[i], b[jj], acc[i][jj]);
    }
    __syncthreads();

    // relu + bias -> s_x as hidden [j][n]; load Wn2 (stride 64)
    #pragma unroll
    for (int jj = 0; jj < 4; jj++) {
        int j = lane + 32 * jj;
        float bv = s_b1[j];
        #pragma unroll
        for (int i = 0; i < 8; i++) {
            float v = acc[i][jj] + bv;
            s_x[j * 65 + w * 8 + i] = v > 0.0f ? v : 0.0f;
        }
    }
    #pragma unroll
    for (int p = 0; p < 32; p++) {              // Wn2: 128*64
        int lin = p * 256 + tid;
        s_w[lin] = Wn2[lin];
    }
    __syncthreads();

    // GEMM_B: out[64 n][64 o], K=128
    float acc2[8][2];
    #pragma unroll
    for (int i = 0; i < 8; i++) { acc2[i][0] = 0.0f; acc2[i][1] = 0.0f; }
    #pragma unroll 4
    for (int j = 0; j < 128; j++) {
        float b0 = s_w[j * 64 + lane];
        float b1 = s_w[j * 64 + lane + 32];
        #pragma unroll
        for (int i = 0; i < 8; i++) {
            float a = s_x[j * 65 + w * 8 + i];
            acc2[i][0] = fmaf(a, b0, acc2[i][0]);
            acc2[i][1] = fmaf(a, b1, acc2[i][1]);
        }
    }
    float bb0 = s_b2[lane], bb1 = s_b2[lane + 32];
    #pragma unroll
    for (int i = 0; i < 8; i++) {
        int ng = n0 + w * 8 + i;
        if (ng < NN) {
            out_n[ng * 64 + lane]      = acc2[i][0] + bb0;
            out_n[ng * 64 + lane + 32] = acc2[i][1] + bb1;
        }
    }
}

// ---------------------------------------------------------------- launch
extern "C" void kernel_launch(void* const* d_in, const int* in_sizes, int n_in,
                              void* d_out, int out_size)
{
    const float* nf  = (const float*)d_in[0];
    const float* ef  = (const float*)d_in[1];
    const int*   src = (const int*)d_in[2];
    const int*   dst = (const int*)d_in[3];
    const float* We1 = (const float*)d_in[4];
    const float* be1 = (const float*)d_in[5];
    const float* We2 = (const float*)d_in[6];
    const float* be2 = (const float*)d_in[7];
    const float* Wa1 = (const float*)d_in[8];
    const float* ba1 = (const float*)d_in[9];
    const float* Wa2 = (const float*)d_in[10];
    const float* ba2 = (const float*)d_in[11];
    const float* Wn1 = (const float*)d_in[12];
    const float* bn1 = (const float*)d_in[13];
    const float* Wn2 = (const float*)d_in[14];
    const float* bn2 = (const float*)d_in[15];

    float* out_n = (float*)d_out;                       // uh_n: [50000, 64]
    float* out_e = (float*)d_out + (size_t)NN * DOUT;   // uh_e: [800000, 64]

    cudaFuncSetAttribute(k_edge, cudaFuncAttributeMaxDynamicSharedMemorySize, EDGE_SMEM_BYTES);
    cudaFuncSetAttribute(k_node, cudaFuncAttributeMaxDynamicSharedMemorySize, NODE_SMEM_BYTES);

    k_init<<<(NN * 64 + 255) / 256, 256>>>();
    k_edge<<<NE / 64, 256, EDGE_SMEM_BYTES>>>(nf, ef, src, dst,
                                              We1, be1, We2, be2,
                                              Wa1, ba1, Wa2, ba2, out_e);
    k_soft<<<(NE * 32) / 256, 256>>>(out_e, dst);
    k_node<<<(NN + 63) / 64, 256, NODE_SMEM_BYTES>>>(nf, Wn1, bn1, Wn2, bn2, out_n);
}

// round 10
// speedup vs baseline: 1.0479x; 1.0479x over previous
#include <cuda_runtime.h>
#include <math.h>

#define NN 50000
#define NE 800000
#define DIN 64
#define EIN 32
#define EOUT 64
#define DOUT 64

// scratch (device globals: no allocation allowed)
__device__ float g_logit[NE];
__device__ float g_m[NN];
__device__ float g_denom[NN];
__device__ float g_aggraw[NN * 64];

__device__ __forceinline__ void atomicMaxF(float* addr, float v) {
    if (v >= 0.0f) atomicMax((int*)addr, __float_as_int(v));
    else           atomicMin((unsigned int*)addr, __float_as_uint(v));
}

// ---- packed f32x2 helpers (Blackwell FFMA2; PTX-only) ----
__device__ __forceinline__ unsigned long long pk2(float x, float y) {
    unsigned long long r;
    asm("mov.b64 %0, {%1, %2};" : "=l"(r) : "f"(x), "f"(y));
    return r;
}
__device__ __forceinline__ unsigned long long fma2(unsigned long long a,
                                                   unsigned long long b,
                                                   unsigned long long c) {
    unsigned long long d;
    asm("fma.rn.f32x2 %0, %1, %2, %3;" : "=l"(d) : "l"(a), "l"(b), "l"(c));
    return d;
}
__device__ __forceinline__ void upk2(unsigned long long v, float& x, float& y) {
    asm("mov.b64 {%0, %1}, %2;" : "=f"(x), "=f"(y) : "l"(v));
}

// ---------------------------------------------------------------- init
__global__ void k_init() {
    int i = blockIdx.x * 256 + threadIdx.x;
    if (i < NN) { g_m[i] = -INFINITY; g_denom[i] = 0.0f; }
    if (i < NN * 64) g_aggraw[i] = 0.0f;
}

// ---------------------------------------------------------------- edge kernel
// 64 edges per CTA, 256 threads. smem layout (floats), row stride 66 (even ->
// 8B-aligned edge pairs for LDS.64):
//   s_in  : 160*66 = 10560  (e_in transposed [k][e]; reused for We2 [j][o] stride 66)
//   s_h   : 256*66 = 16896  (hidden transposed [j][e], after relu+bias)
//   s_w   :   8*256 = 2048  (layer-1 weight chunk)
//   s_b1  : 256, s_be2: 64, s_wa2: 128, s_ba2: 1, s_src/s_dst: 64 ints each
#define EDGE_SMEM_FLOATS 30084
#define EDGE_SMEM_BYTES (EDGE_SMEM_FLOATS * 4)

__global__ void __launch_bounds__(256, 1) k_edge(
    const float* __restrict__ nf, const float* __restrict__ ef,
    const int* __restrict__ src, const int* __restrict__ dst,
    const float* __restrict__ We1, const float* __restrict__ be1,
    const float* __restrict__ We2, const float* __restrict__ be2,
    const float* __restrict__ Wa1, const float* __restrict__ ba1,
    const float* __restrict__ Wa2, const float* __restrict__ ba2,
    float* __restrict__ out_e)
{
    extern __shared__ float smem[];
    float* s_in  = smem;             // 10560
    float* s_h   = smem + 10560;     // 16896
    float* s_w   = smem + 27456;     // 2048
    float* s_b1  = smem + 29504;     // 256
    float* s_be2 = smem + 29760;     // 64
    float* s_wa2 = smem + 29824;     // 128
    float* s_ba2 = smem + 29952;     // 1
    int*   s_src = (int*)(smem + 29953);  // 64
    int*   s_dst = (int*)(smem + 30017);  // 64

    const int tid  = threadIdx.x;
    const int lane = tid & 31;
    const int w    = tid >> 5;        // warp id 0..7
    const int e0   = blockIdx.x * 64;

    if (tid < 64)        s_src[tid]      = src[e0 + tid];
    else if (tid < 128)  s_dst[tid - 64] = dst[e0 + tid - 64];
    s_b1[tid] = (tid < 128) ? be1[tid] : ba1[tid - 128];
    if (tid < 64)  s_be2[tid] = be2[tid];
    if (tid < 128) s_wa2[tid] = Wa2[tid];
    if (tid == 0)  s_ba2[0]   = ba2[0];
    __syncthreads();

    // gather e_in = [nf[src] | nf[dst] | ef] transposed into s_in[k][e]
    #pragma unroll
    for (int p = 0; p < 40; ++p) {
        int lin = p * 256 + tid;          // 64*160 = 10240 total
        int e = lin / 160;
        int k = lin - e * 160;
        float v;
        if (k < 64)       v = nf[s_src[e] * 64 + k];
        else if (k < 128) v = nf[s_dst[e] * 64 + (k - 64)];
        else              v = ef[(e0 + e) * 32 + (k - 128)];
        s_in[k * 66 + e] = v;
    }

    // GEMM1: hidden[64 e][256 j] = e_in @ [We1|Wa1], K=160   (packed f32x2)
    // warp w owns edges w*8..w*8+7 (4 pairs); thread owns j = lane + 32*jj
    unsigned long long acc[4][8];
    #pragma unroll
    for (int i = 0; i < 4; i++)
        #pragma unroll
        for (int j = 0; j < 8; j++) acc[i][j] = 0ull;

    for (int k0 = 0; k0 < 160; k0 += 8) {
        __syncthreads();
        #pragma unroll
        for (int p = 0; p < 8; p++) {
            int k = k0 + p;
            s_w[p * 256 + tid] = (tid < 128) ? We1[k * 128 + tid]
                                             : Wa1[k * 128 + (tid - 128)];
        }
        __syncthreads();
        #pragma unroll
        for (int kk = 0; kk < 8; kk++) {
            const float* rowA = s_in + (k0 + kk) * 66 + w * 8;
            unsigned long long a[4];
            #pragma unroll
            for (int ip = 0; ip < 4; ip++)
                a[ip] = *(const unsigned long long*)(rowA + 2 * ip);
            const float* rowB = s_w + kk * 256 + lane;
            #pragma unroll
            for (int jj = 0; jj < 8; jj++) {
                float bv = rowB[32 * jj];
                unsigned long long bd = pk2(bv, bv);
                #pragma unroll
                for (int ip = 0; ip < 4; ip++)
                    acc[ip][jj] = fma2(a[ip], bd, acc[ip][jj]);
            }
        }
    }
    __syncthreads();

    // relu(acc + bias) -> s_h[j][e] (paired STS.64); load We2 into s_in (stride 66)
    #pragma unroll
    for (int jj = 0; jj < 8; jj++) {
        int j = lane + 32 * jj;
        float bv = s_b1[j];
        #pragma unroll
        for (int ip = 0; ip < 4; ip++) {
            float v0, v1;
            upk2(acc[ip][jj], v0, v1);
            v0 = fmaxf(v0 + bv, 0.0f);
            v1 = fmaxf(v1 + bv, 0.0f);
            *(float2*)(s_h + j * 66 + w * 8 + 2 * ip) = make_float2(v0, v1);
        }
    }
    float* s_w2 = s_in;
    #pragma unroll
    for (int p = 0; p < 32; p++) {
        int lin = p * 256 + tid;          // 128*64 = 8192
        int j = lin >> 6, o = lin & 63;
        s_w2[j * 66 + o] = We2[lin];
    }
    __syncthreads();

    // GEMM2: uh_e[64 e][64 o] = relu_h[:, :128] @ We2, K=128   (packed f32x2)
    unsigned long long acc2[4][2];
    #pragma unroll
    for (int i = 0; i < 4; i++) { acc2[i][0] = 0ull; acc2[i][1] = 0ull; }
    #pragma unroll 4
    for (int j = 0; j < 128; j++) {
        float b0 = s_w2[j * 66 + lane];
        float b1 = s_w2[j * 66 + lane + 32];
        unsigned long long b0d = pk2(b0, b0);
        unsigned long long b1d = pk2(b1, b1);
        const float* rowH = s_h + j * 66 + w * 8;
        #pragma unroll
        for (int ip = 0; ip < 4; ip++) {
            unsigned long long a = *(const unsigned long long*)(rowH + 2 * ip);
            acc2[ip][0] = fma2(a, b0d, acc2[ip][0]);
            acc2[ip][1] = fma2(a, b1d, acc2[ip][1]);
        }
    }
    float bb0 = s_be2[lane], bb1 = s_be2[lane + 32];
    #pragma unroll
    for (int ip = 0; ip < 4; ip++) {
        float x0, x1, y0, y1;
        upk2(acc2[ip][0], x0, x1);
        upk2(acc2[ip][1], y0, y1);
        int eg = e0 + w * 8 + 2 * ip;
        out_e[(size_t)eg * 64 + lane]            = x0 + bb0;
        out_e[(size_t)eg * 64 + lane + 32]       = y0 + bb1;
        out_e[(size_t)(eg + 1) * 64 + lane]      = x1 + bb0;
        out_e[(size_t)(eg + 1) * 64 + lane + 32] = y1 + bb1;
    }

    // attention logit: relu_h[:, 128:256] . Wa2 + ba2  (threads 0..63, one edge each)
    if (tid < 64) {
        float lg = s_ba2[0];
        #pragma unroll 4
        for (int j = 0; j < 128; j++)
            lg = fmaf(s_h[(128 + j) * 66 + tid], s_wa2[j], lg);
        g_logit[e0 + tid] = lg;
        atomicMaxF(&g_m[s_dst[tid]], lg);
    }
}

// ---------------------------------------------------------------- softmax + scatter
// one warp per edge; warp-uniform broadcast loads (no shuffles)
__global__ void k_soft(const float* __restrict__ out_e, const int* __restrict__ dst) {
    int wid = (blockIdx.x * blockDim.x + threadIdx.x) >> 5;
    if (wid >= NE) return;
    int lane = threadIdx.x & 31;
    int e = wid;
    int d = dst[e];                               // broadcast (uniform addr)
    float ex = expf(g_logit[e] - g_m[d]);         // broadcast
    if (lane == 0) atomicAdd(&g_denom[d], ex);
    const float2* pe = (const float2*)(out_e + (size_t)e * 64);
    float2 v = pe[lane];
    atomicAdd(&g_aggraw[d * 64 + 2 * lane],     v.x * ex);
    atomicAdd(&g_aggraw[d * 64 + 2 * lane + 1], v.y * ex);
}

// ---------------------------------------------------------------- node kernel
// 64 nodes per CTA, 256 threads. (unchanged — 3.5% of runtime)
#define NODE_SMEM_FLOATS 24960
#define NODE_SMEM_BYTES (NODE_SMEM_FLOATS * 4)

__global__ void __launch_bounds__(256, 1) k_node(
    const float* __restrict__ nf,
    const float* __restrict__ Wn1, const float* __restrict__ bn1,
    const float* __restrict__ Wn2, const float* __restrict__ bn2,
    float* __restrict__ out_n)
{
    extern __shared__ float smem[];
    float* s_x   = smem;           // 8320 (x [k][n]; reused as hidden [j][n])
    float* s_w   = smem + 8320;    // 16384 (Wn1; reused for Wn2)
    float* s_b1  = smem + 24704;   // 128
    float* s_b2  = smem + 24832;   // 64
    float* s_inv = smem + 24896;   // 64

    const int tid = threadIdx.x, lane = tid & 31, w = tid >> 5;
    const int n0 = blockIdx.x * 64;

    if (tid < 128)      s_b1[tid]       = bn1[tid];
    else if (tid < 192) s_b2[tid - 128] = bn2[tid - 128];
    if (tid < 64) {
        int ng = n0 + tid;
        s_inv[tid] = (ng < NN) ? 1.0f / fmaxf(g_denom[ng], 1e-38f) : 0.0f;
    }
    #pragma unroll
    for (int p = 0; p < 64; p++) {              // Wn1: 128*128
        int lin = p * 256 + tid;
        s_w[lin] = Wn1[lin];
    }
    __syncthreads();

    // x = [agg | nf] transposed into s_x[k][n]
    #pragma unroll
    for (int p = 0; p < 32; p++) {
        int lin = p * 256 + tid;                // 64*128
        int n = lin >> 7, k = lin & 127;
        int ng = n0 + n;
        float v = 0.0f;
        if (ng < NN) {
            if (k < 64) v = g_aggraw[ng * 64 + k] * s_inv[n];
            else        v = nf[ng * 64 + (k - 64)];
        }
        s_x[k * 65 + n] = v;
    }
    __syncthreads();

    // GEMM_A: hidden[64 n][128 j], K=128
    float acc[8][4];
    #pragma unroll
    for (int i = 0; i < 8; i++)
        #pragma unroll
        for (int j = 0; j < 4; j++) acc[i][j] = 0.0f;
    #pragma unroll 4
    for (int k = 0; k < 128; k++) {
        float a[8], b[4];
        #pragma unroll
        for (int i = 0; i < 8; i++) a[i] = s_x[k * 65 + w * 8 + i];
        #pragma unroll
        for (int jj = 0; jj < 4; jj++) b[jj] = s_w[k * 128 + lane + 32 * jj];
        #pragma unroll
        for (int i = 0; i < 8; i++)
            #pragma unroll
            for (int jj = 0; jj < 4; jj++)
                acc[i][jj] = fmaf(a[i], b[jj], acc[i][jj]);
    }
    __syncthreads();

    // relu + bias -> s_x as hidden [j][n]; load Wn2 (stride 64)
    #pragma unroll
    for (int jj = 0; jj < 4; jj++) {
        int j = lane + 32 * jj;
        float bv = s_b1[j];
        #pragma unroll
        for (int i = 0; i < 8; i++) {
            float v = acc[i][jj] + bv;
            s_x[j * 65 + w * 8 + i] = v > 0.0f ? v : 0.0f;
        }
    }
    #pragma unroll
    for (int p = 0; p < 32; p++) {              // Wn2: 128*64
        int lin = p * 256 + tid;
        s_w[lin] = Wn2[lin];
    }
    __syncthreads();

    // GEMM_B: out[64 n][64 o], K=128
    float acc2[8][2];
    #pragma unroll
    for (int i = 0; i < 8; i++) { acc2[i][0] = 0.0f; acc2[i][1] = 0.0f; }
    #pragma unroll 4
    for (int j = 0; j < 128; j++) {
        float b0 = s_w[j * 64 + lane];
        float b1 = s_w[j * 64 + lane + 32];
        #pragma unroll
        for (int i = 0; i < 8; i++) {
            float a = s_x[j * 65 + w * 8 + i];
            acc2[i][0] = fmaf(a, b0, acc2[i][0]);
            acc2[i][1] = fmaf(a, b1, acc2[i][1]);
        }
    }
    float bb0 = s_b2[lane], bb1 = s_b2[lane + 32];
    #pragma unroll
    for (int i = 0; i < 8; i++) {
        int ng = n0 + w * 8 + i;
        if (ng < NN) {
            out_n[ng * 64 + lane]      = acc2[i][0] + bb0;
            out_n[ng * 64 + lane + 32] = acc2[i][1] + bb1;
        }
    }
}

// ---------------------------------------------------------------- launch
extern "C" void kernel_launch(void* const* d_in, const int* in_sizes, int n_in,
                              void* d_out, int out_size)
{
    const float* nf  = (const float*)d_in[0];
    const float* ef  = (const float*)d_in[1];
    const int*   src = (const int*)d_in[2];
    const int*   dst = (const int*)d_in[3];
    const float* We1 = (const float*)d_in[4];
    const float* be1 = (const float*)d_in[5];
    const float* We2 = (const float*)d_in[6];
    const float* be2 = (const float*)d_in[7];
    const float* Wa1 = (const float*)d_in[8];
    const float* ba1 = (const float*)d_in[9];
    const float* Wa2 = (const float*)d_in[10];
    const float* ba2 = (const float*)d_in[11];
    const float* Wn1 = (const float*)d_in[12];
    const float* bn1 = (const float*)d_in[13];
    const float* Wn2 = (const float*)d_in[14];
    const float* bn2 = (const float*)d_in[15];

    float* out_n = (float*)d_out;                       // uh_n: [50000, 64]
    float* out_e = (float*)d_out + (size_t)NN * DOUT;   // uh_e: [800000, 64]

    cudaFuncSetAttribute(k_edge, cudaFuncAttributeMaxDynamicSharedMemorySize, EDGE_SMEM_BYTES);
    cudaFuncSetAttribute(k_node, cudaFuncAttributeMaxDynamicSharedMemorySize, NODE_SMEM_BYTES);

    k_init<<<(NN * 64 + 255) / 256, 256>>>();
    k_edge<<<NE / 64, 256, EDGE_SMEM_BYTES>>>(nf, ef, src, dst,
                                              We1, be1, We2, be2,
                                              Wa1, ba1, Wa2, ba2, out_e);
    k_soft<<<(NE * 32) / 256, 256>>>(out_e, dst);
    k_node<<<(NN + 63) / 64, 256, NODE_SMEM_BYTES>>>(nf, Wn1, bn1, Wn2, bn2, out_n);
}